// round 6
// baseline (speedup 1.0000x reference)
#include <cuda_runtime.h>
#include <cuda_fp16.h>
#include <cstdint>

// ===========================================================================
// DenseAE: out = sigmoid(relu(ksparse64(relu(X@We1+be1))@Wd1+bd1)@Wd2+bd2)
// B=4096, D=12288, HID=1024, k=64
// GEMMs: double-fp16 split (hi/lo), 3 HMMA per k16 pair.
// R6: deep cp.async pipeline (BK=32 x 6 stages), loads issued BEFORE compute,
//     single syncthreads per chunk, exact wait_group accounting.
// ===========================================================================

#define BM 128
#define BN 128
#define BK 32
#define STAGES 6
#define STAGE_BYTES 32768
#define OFF_AH 0
#define OFF_AL 8192
#define OFF_BH 16384
#define OFF_BL 24576
#define SMEM_ALLOC (STAGES * STAGE_BYTES + 1024)

// ---------------- scratch (device globals; no runtime allocation) ----------
__device__ __half g_Xh[4096L * 12288];
__device__ __half g_Xl[4096L * 12288];
__device__ __half g_W1h[1024L * 12288];   // We1^T [1024, 12288]
__device__ __half g_W1l[1024L * 12288];
__device__ __half g_W2h[1024L * 1024];    // Wd1^T [1024, 1024]
__device__ __half g_W2l[1024L * 1024];
__device__ __half g_W3h[12288L * 1024];   // Wd2^T [12288, 1024]
__device__ __half g_W3l[12288L * 1024];
__device__ float  g_h [4096L * 1024];
__device__ __half g_hh[4096L * 1024];
__device__ __half g_hl[4096L * 1024];
__device__ __half g_dh[4096L * 1024];
__device__ __half g_dl[4096L * 1024];

// ---------------- helpers ---------------------------------------------------
__device__ __forceinline__ uint32_t smem_u32(const void* p) {
    uint32_t a;
    asm("{ .reg .u64 t; cvta.to.shared.u64 t, %1; cvt.u32.u64 %0, t; }" : "=r"(a) : "l"(p));
    return a;
}
__device__ __forceinline__ void cpasync16(uint32_t dst, const void* src) {
    asm volatile("cp.async.cg.shared.global [%0], [%1], 16;" :: "r"(dst), "l"(src));
}
#define CP_COMMIT() asm volatile("cp.async.commit_group;")
#define CP_WAIT4()  asm volatile("cp.async.wait_group 4;")

// Swizzled offset of (row, 16B-chunk) in a [128 x 64B] tile:
// 128B lines hold row pairs; chunk-within-line XOR'd by line&7 (SW128).
__device__ __forceinline__ uint32_t tile_off(int row, int ch) {
    return (uint32_t)(((row >> 1) << 7) +
                      (((((row & 1) << 2) | ch) ^ ((row >> 1) & 7)) << 4));
}

__device__ __forceinline__ void ldsm4(uint32_t& r0, uint32_t& r1, uint32_t& r2,
                                      uint32_t& r3, uint32_t a) {
    asm volatile("ldmatrix.sync.aligned.m8n8.x4.shared.b16 {%0,%1,%2,%3}, [%4];"
                 : "=r"(r0), "=r"(r1), "=r"(r2), "=r"(r3) : "r"(a));
}
__device__ __forceinline__ void mma_f16_f32(float c[4], const uint32_t a[4],
                                            const uint32_t b[2]) {
    asm volatile(
        "mma.sync.aligned.m16n8k16.row.col.f32.f16.f16.f32 "
        "{%0,%1,%2,%3}, {%4,%5,%6,%7}, {%8,%9}, {%0,%1,%2,%3};\n"
        : "+f"(c[0]), "+f"(c[1]), "+f"(c[2]), "+f"(c[3])
        : "r"(a[0]), "r"(a[1]), "r"(a[2]), "r"(a[3]), "r"(b[0]), "r"(b[1]));
}
__device__ __forceinline__ void mma_f16_f16(uint32_t c[2], const uint32_t a[4],
                                            const uint32_t b[2]) {
    asm volatile(
        "mma.sync.aligned.m16n8k16.row.col.f16.f16.f16.f16 "
        "{%0,%1}, {%2,%3,%4,%5}, {%6,%7}, {%0,%1};\n"
        : "+r"(c[0]), "+r"(c[1])
        : "r"(a[0]), "r"(a[1]), "r"(a[2]), "r"(a[3]), "r"(b[0]), "r"(b[1]));
}
__device__ __forceinline__ void split_h(float x, __half& hi, __half& lo) {
    hi = __float2half_rn(x);
    lo = __float2half_rn(x - __half2float(hi));   // exact residual capture
}

// ===========================================================================
// GEMM: C[M,N] = act(A[M,K] @ Bt[N,K]^T + bias); A,Bt given as fp16 hi/lo.
// ACT: 0 relu, 1 sigmoid.  OUT_SPLIT: write fp16 (hi,lo) pair instead of f32.
// ===========================================================================
template <int ACT, int OUT_SPLIT>
__global__ void __launch_bounds__(256, 1)
gemm_fp16x2(const __half* __restrict__ Ah, const __half* __restrict__ Al,
            const __half* __restrict__ Bh, const __half* __restrict__ Bl,
            const float* __restrict__ bias, float* __restrict__ C0,
            __half* __restrict__ Sh, __half* __restrict__ Sl,
            int M, int N, int K)
{
    extern __shared__ char smem_raw[];
    const uint32_t sbase = (smem_u32(smem_raw) + 1023u) & ~1023u;
    const int tid = threadIdx.x, lane = tid & 31, warp = tid >> 5;
    const int wm = warp >> 1;            // 0..3 : M tiles of 32
    const int wn = warp & 1;             // 0..1 : N tiles of 64
    const long bm = (long)blockIdx.y * BM;
    const long bn = (long)blockIdx.x * BN;
    const int NC = K / BK;

    // ---- per-thread load geometry: row = tid>>1, chunks (tid&1)*2 + {0,1} ---
    const int lrow = tid >> 1;
    const int lch  = (tid & 1) * 2;
    const uint32_t so0 = tile_off(lrow, lch);
    const uint32_t so1 = tile_off(lrow, lch + 1);

    auto load_stage = [&](int c) {
        const uint32_t st = sbase + (c % STAGES) * STAGE_BYTES;
        const long kt = (long)c * BK;
        const long goA = (bm + lrow) * (long)K + kt + lch * 8;
        const long goB = (bn + lrow) * (long)K + kt + lch * 8;
        cpasync16(st + OFF_AH + so0, Ah + goA);
        cpasync16(st + OFF_AH + so1, Ah + goA + 8);
        cpasync16(st + OFF_AL + so0, Al + goA);
        cpasync16(st + OFF_AL + so1, Al + goA + 8);
        cpasync16(st + OFF_BH + so0, Bh + goB);
        cpasync16(st + OFF_BH + so1, Bh + goB + 8);
        cpasync16(st + OFF_BL + so0, Bl + goB);
        cpasync16(st + OFF_BL + so1, Bl + goB + 8);
        CP_COMMIT();
    };

    // ---- ldmatrix lane geometry (same logical layout as before) ----
    const int agrp = lane >> 3, aw = lane & 7;
    const int a_rbase = wm * 32 + (agrp & 1) * 8 + aw;      // + mi*16
    const int a_kc    = agrp >> 1;                          // 16B chunk LSB
    const int b_rbase = wn * 64 + ((lane >> 3) >> 1) * 8 + (lane & 7); // + nj*16
    const int b_kc    = (lane >> 3) & 1;

    float acc[2][8][4];
    uint32_t acx[2][8][2];               // fp16 cross-term accumulators
#pragma unroll
    for (int mi = 0; mi < 2; mi++)
#pragma unroll
        for (int ni = 0; ni < 8; ni++) {
#pragma unroll
            for (int j = 0; j < 4; j++) acc[mi][ni][j] = 0.0f;
            acx[mi][ni][0] = 0u;
            acx[mi][ni][1] = 0u;
        }

    auto compute = [&](int c) {
        const uint32_t st = sbase + (c % STAGES) * STAGE_BYTES;
#pragma unroll
        for (int kk = 0; kk < 2; kk++) {
            uint32_t ah[2][4], al[2][4];
#pragma unroll
            for (int mi = 0; mi < 2; mi++) {
                const uint32_t o = tile_off(a_rbase + mi * 16, kk * 2 + a_kc);
                ldsm4(ah[mi][0], ah[mi][1], ah[mi][2], ah[mi][3], st + OFF_AH + o);
                ldsm4(al[mi][0], al[mi][1], al[mi][2], al[mi][3], st + OFF_AL + o);
            }
            uint32_t bh[8][2], bl[8][2];
#pragma unroll
            for (int nj = 0; nj < 4; nj++) {
                const uint32_t o = tile_off(b_rbase + nj * 16, kk * 2 + b_kc);
                ldsm4(bh[2 * nj][0], bh[2 * nj][1], bh[2 * nj + 1][0],
                      bh[2 * nj + 1][1], st + OFF_BH + o);
                ldsm4(bl[2 * nj][0], bl[2 * nj][1], bl[2 * nj + 1][0],
                      bl[2 * nj + 1][1], st + OFF_BL + o);
            }
#pragma unroll
            for (int mi = 0; mi < 2; mi++)
#pragma unroll
                for (int ni = 0; ni < 8; ni++) {
                    mma_f16_f32(acc[mi][ni], ah[mi], bh[ni]);   // hi*hi (f32)
                    mma_f16_f16(acx[mi][ni], ah[mi], bl[ni]);   // hi*lo (f16)
                    mma_f16_f16(acx[mi][ni], al[mi], bh[ni]);   // lo*hi (f16)
                }
        }
    };

    // ---- prologue: fill 5 of 6 stages ----
#pragma unroll
    for (int s = 0; s < STAGES - 1; s++) load_stage(s);

    for (int c = 0; c < NC; c++) {
        CP_WAIT4();                 // stage c guaranteed complete
        __syncthreads();            // all warps see data; prev compute done
        if (c + STAGES - 1 < NC) load_stage(c + STAGES - 1);
        else                     CP_COMMIT();   // keep group accounting exact
        compute(c);
    }

    // ---- epilogue: merge cross-acc, bias, activation ----
    const int l4 = lane >> 2, l2 = (lane & 3) * 2;
#pragma unroll
    for (int mi = 0; mi < 2; mi++) {
        const long rg = bm + wm * 32 + mi * 16 + l4;
#pragma unroll
        for (int ni = 0; ni < 8; ni++) {
            const long cg = bn + wn * 64 + ni * 8 + l2;
            const __half2 cx0 = *(const __half2*)&acx[mi][ni][0];
            const __half2 cx1 = *(const __half2*)&acx[mi][ni][1];
            const float b0 = bias[cg], b1 = bias[cg + 1];
            float x0 = acc[mi][ni][0] + __low2float(cx0)  + b0;
            float x1 = acc[mi][ni][1] + __high2float(cx0) + b1;
            float x2 = acc[mi][ni][2] + __low2float(cx1)  + b0;
            float x3 = acc[mi][ni][3] + __high2float(cx1) + b1;
            if (ACT == 0) {
                x0 = fmaxf(x0, 0.f); x1 = fmaxf(x1, 0.f);
                x2 = fmaxf(x2, 0.f); x3 = fmaxf(x3, 0.f);
            } else {
                x0 = 1.f / (1.f + __expf(-x0));
                x1 = 1.f / (1.f + __expf(-x1));
                x2 = 1.f / (1.f + __expf(-x2));
                x3 = 1.f / (1.f + __expf(-x3));
            }
            const long o0 = rg * (long)N + cg;
            const long o1 = (rg + 8) * (long)N + cg;
            if (OUT_SPLIT) {
                __half h0, l0, h1, l1;
                split_h(x0, h0, l0); split_h(x1, h1, l1);
                *(__half2*)&Sh[o0] = __halves2half2(h0, h1);
                *(__half2*)&Sl[o0] = __halves2half2(l0, l1);
                split_h(x2, h0, l0); split_h(x3, h1, l1);
                *(__half2*)&Sh[o1] = __halves2half2(h0, h1);
                *(__half2*)&Sl[o1] = __halves2half2(l0, l1);
            } else {
                *(float2*)&C0[o0] = make_float2(x0, x1);
                *(float2*)&C0[o1] = make_float2(x2, x3);
            }
        }
    }
}

// ===========================================================================
// X [M,K] fp32 -> (hi, lo) fp16 arrays (vectorized, grid-stride)
// ===========================================================================
__global__ void __launch_bounds__(256)
split_kernel(const float* __restrict__ x, __half* __restrict__ hi,
             __half* __restrict__ lo, long n4)
{
    const long stride = (long)gridDim.x * 256;
    for (long i = blockIdx.x * 256L + threadIdx.x; i < n4; i += stride) {
        float4 v = ((const float4*)x)[i];
        __half h0, l0, h1, l1, h2, l2, h3, l3;
        split_h(v.x, h0, l0); split_h(v.y, h1, l1);
        split_h(v.z, h2, l2); split_h(v.w, h3, l3);
        ((__half2*)hi)[2 * i]     = __halves2half2(h0, h1);
        ((__half2*)hi)[2 * i + 1] = __halves2half2(h2, h3);
        ((__half2*)lo)[2 * i]     = __halves2half2(l0, l1);
        ((__half2*)lo)[2 * i + 1] = __halves2half2(l2, l3);
    }
}

// ===========================================================================
// W [K,N] fp32 -> Wt hi/lo [N,K] fp16 (transpose + split), 32x32 tiles
// ===========================================================================
__global__ void __launch_bounds__(256)
transpose_split_kernel(const float* __restrict__ W, __half* __restrict__ Wth,
                       __half* __restrict__ Wtl, int K, int N)
{
    __shared__ float t[32][33];
    const int tx = threadIdx.x, ty = threadIdx.y;
    const long n0 = (long)blockIdx.x * 32, k0 = (long)blockIdx.y * 32;
#pragma unroll
    for (int j = 0; j < 4; j++)
        t[ty + 8 * j][tx] = W[(k0 + ty + 8 * j) * N + n0 + tx];
    __syncthreads();
#pragma unroll
    for (int j = 0; j < 4; j++) {
        const float v = t[tx][ty + 8 * j];
        __half h, l;
        split_h(v, h, l);
        const long o = (n0 + ty + 8 * j) * K + k0 + tx;
        Wth[o] = h;
        Wtl[o] = l;
    }
}

// ===========================================================================
// Exact per-row top-64 keep (radix select, nonneg) + fp16 hi/lo split output
// ===========================================================================
__global__ void __launch_bounds__(256)
topk64_split_kernel(const float* __restrict__ h, __half* __restrict__ hhi,
                    __half* __restrict__ hlo)
{
    __shared__ float vals[1024];
    __shared__ int hist[256];
    __shared__ int s_k;
    __shared__ unsigned s_prefix;

    const float* row = h + (long)blockIdx.x * 1024;
    const int tid = threadIdx.x;

#pragma unroll
    for (int i = tid; i < 1024; i += 256) vals[i] = row[i];
    if (tid == 0) { s_k = 64; s_prefix = 0u; }
    __syncthreads();

#pragma unroll
    for (int shift = 24; shift >= 0; shift -= 8) {
        hist[tid] = 0;
        __syncthreads();
        const unsigned hmask = (shift == 24) ? 0u : (0xFFFFFFFFu << (shift + 8));
        const unsigned pfx = s_prefix;
#pragma unroll
        for (int i = tid; i < 1024; i += 256) {
            const unsigned u = __float_as_uint(vals[i]);
            if ((u & hmask) == pfx)
                atomicAdd(&hist[(u >> shift) & 255], 1);
        }
        __syncthreads();
        if (tid == 0) {
            int k = s_k, cum = 0, d;
            for (d = 255; d > 0; d--) {
                const int c = hist[d];
                if (cum + c >= k) break;
                cum += c;
            }
            s_prefix = pfx | ((unsigned)d << shift);
            s_k = k - cum;
        }
        __syncthreads();
    }

    const float thr = __uint_as_float(s_prefix);
    const long base = (long)blockIdx.x * 1024;
#pragma unroll
    for (int i = tid; i < 1024; i += 256) {
        const float v = vals[i];
        const float kept = (v >= thr) ? v : 0.0f;
        __half hi, lo;
        split_h(kept, hi, lo);
        hhi[base + i] = hi;
        hlo[base + i] = lo;
    }
}

// ===========================================================================
extern "C" void kernel_launch(void* const* d_in, const int* in_sizes, int n_in,
                              void* d_out, int out_size)
{
    const float* X   = (const float*)d_in[0];   // [4096, 12288]
    const float* We1 = (const float*)d_in[1];   // [12288, 1024]
    const float* be1 = (const float*)d_in[2];
    const float* Wd1 = (const float*)d_in[3];   // [1024, 1024]
    const float* bd1 = (const float*)d_in[4];
    const float* Wd2 = (const float*)d_in[5];   // [1024, 12288]
    const float* bd2 = (const float*)d_in[6];
    float* out = (float*)d_out;                 // [4096, 12288]

    __half *Xh, *Xl, *W1h, *W1l, *W2h, *W2l, *W3h, *W3l, *hh, *hl, *dh, *dl;
    float* h;
    cudaGetSymbolAddress((void**)&Xh, g_Xh);   cudaGetSymbolAddress((void**)&Xl, g_Xl);
    cudaGetSymbolAddress((void**)&W1h, g_W1h); cudaGetSymbolAddress((void**)&W1l, g_W1l);
    cudaGetSymbolAddress((void**)&W2h, g_W2h); cudaGetSymbolAddress((void**)&W2l, g_W2l);
    cudaGetSymbolAddress((void**)&W3h, g_W3h); cudaGetSymbolAddress((void**)&W3l, g_W3l);
    cudaGetSymbolAddress((void**)&h, g_h);
    cudaGetSymbolAddress((void**)&hh, g_hh);   cudaGetSymbolAddress((void**)&hl, g_hl);
    cudaGetSymbolAddress((void**)&dh, g_dh);   cudaGetSymbolAddress((void**)&dl, g_dl);

    cudaFuncSetAttribute(gemm_fp16x2<0, 0>, cudaFuncAttributeMaxDynamicSharedMemorySize, SMEM_ALLOC);
    cudaFuncSetAttribute(gemm_fp16x2<0, 1>, cudaFuncAttributeMaxDynamicSharedMemorySize, SMEM_ALLOC);
    cudaFuncSetAttribute(gemm_fp16x2<1, 0>, cudaFuncAttributeMaxDynamicSharedMemorySize, SMEM_ALLOC);

    const int M = 4096, HID = 1024, D = 12288;

    // ---- operand prep ----
    transpose_split_kernel<<<dim3(HID / 32, D / 32), dim3(32, 8)>>>(We1, W1h, W1l, D, HID);
    transpose_split_kernel<<<dim3(HID / 32, HID / 32), dim3(32, 8)>>>(Wd1, W2h, W2l, HID, HID);
    transpose_split_kernel<<<dim3(D / 32, HID / 32), dim3(32, 8)>>>(Wd2, W3h, W3l, HID, D);
    split_kernel<<<8192, 256>>>(X, Xh, Xl, (long)M * D / 4);

    // ---- layer 1: h = relu(X @ We1 + be1) ----
    gemm_fp16x2<0, 0><<<dim3(HID / BN, M / BM), 256, SMEM_ALLOC>>>(
        Xh, Xl, W1h, W1l, be1, h, nullptr, nullptr, M, HID, D);
    // ---- top-64 keep + split ----
    topk64_split_kernel<<<M, 256>>>(h, hh, hl);
    // ---- layer 2: d = relu(h @ Wd1 + bd1), output pre-split ----
    gemm_fp16x2<0, 1><<<dim3(HID / BN, M / BM), 256, SMEM_ALLOC>>>(
        hh, hl, W2h, W2l, bd1, nullptr, dh, dl, M, HID, HID);
    // ---- layer 3: out = sigmoid(d @ Wd2 + bd2) ----
    gemm_fp16x2<1, 0><<<dim3(D / BN, M / BM), 256, SMEM_ALLOC>>>(
        dh, dl, W3h, W3l, bd2, out, nullptr, nullptr, M, D, HID);
}

// round 7
// speedup vs baseline: 1.4697x; 1.4697x over previous
#include <cuda_runtime.h>
#include <cstdint>

// ===========================================================================
// DenseAE: out = sigmoid(relu(ksparse64(relu(X@We1+be1))@Wd1+bd1)@Wd2+bd2)
// B=4096, D=12288, HID=1024, k=64
// R7: int8 digit-split GEMMs. x ~ s/16256 * (128*a1 + a0); 3 IMMA k32 per
// K=32 (a1b1 in acc1; a1b0+a0b1 share accm; a0b0 dropped ~7e-5).
// Exact s32 accumulation; 2x tensor rate + half operand traffic vs fp16 path.
// ===========================================================================

#define BM 128
#define BN 128
#define BK 64
#define STAGES 3
#define STAGE_BYTES 32768
#define OFF_A1 0
#define OFF_A0 8192
#define OFF_B1 16384
#define OFF_B0 24576
#define SMEM_ALLOC (STAGES * STAGE_BYTES + 1024)

#define QSCALE 16256.0f   // 127*128: a1 in [-127,127], a0 in [-64,64]

// ---------------- scratch (device globals; no runtime allocation) ----------
__device__ __align__(128) int8_t g_X1[4096L * 12288];
__device__ __align__(128) int8_t g_X0[4096L * 12288];
__device__ __align__(128) int8_t g_W1q1[1024L * 12288];  // We1^T digits
__device__ __align__(128) int8_t g_W1q0[1024L * 12288];
__device__ __align__(128) int8_t g_W2q1[1024L * 1024];   // Wd1^T digits
__device__ __align__(128) int8_t g_W2q0[1024L * 1024];
__device__ __align__(128) int8_t g_W3q1[12288L * 1024];  // Wd2^T digits
__device__ __align__(128) int8_t g_W3q0[12288L * 1024];
__device__ float g_h[4096L * 1024];
__device__ float g_d[4096L * 1024];
__device__ __align__(128) int8_t g_h1[4096L * 1024];
__device__ __align__(128) int8_t g_h0[4096L * 1024];
__device__ __align__(128) int8_t g_d1[4096L * 1024];
__device__ __align__(128) int8_t g_d0[4096L * 1024];
__device__ float g_sX[4096];
__device__ float g_sh[4096];
__device__ float g_sd[4096];
__device__ float g_sW1[1024];
__device__ float g_sW2[1024];
__device__ float g_sW3[12288];

// ---------------- helpers ---------------------------------------------------
__device__ __forceinline__ uint32_t smem_u32(const void* p) {
    uint32_t a;
    asm("{ .reg .u64 t; cvta.to.shared.u64 t, %1; cvt.u32.u64 %0, t; }" : "=r"(a) : "l"(p));
    return a;
}
__device__ __forceinline__ void cpasync16(uint32_t dst, const void* src) {
    asm volatile("cp.async.cg.shared.global [%0], [%1], 16;" :: "r"(dst), "l"(src));
}
#define CP_COMMIT() asm volatile("cp.async.commit_group;")
#define CP_WAIT2()  asm volatile("cp.async.wait_group 2;")

// [128 rows x 64B] tile; row pairs share a 128B line; 16B chunks XOR-swizzled.
__device__ __forceinline__ uint32_t tile_off(int row, int ch) {
    const int line = row >> 1;
    const int idx = ((row & 1) << 2) | ch;
    return (uint32_t)((line << 7) + ((idx ^ (line & 7)) << 4));
}

__device__ __forceinline__ void ldsm4(uint32_t& r0, uint32_t& r1, uint32_t& r2,
                                      uint32_t& r3, uint32_t a) {
    asm volatile("ldmatrix.sync.aligned.m8n8.x4.shared.b16 {%0,%1,%2,%3}, [%4];"
                 : "=r"(r0), "=r"(r1), "=r"(r2), "=r"(r3) : "r"(a));
}
__device__ __forceinline__ void mma_s8(int c[4], const uint32_t a[4],
                                       const uint32_t b[2]) {
    asm volatile(
        "mma.sync.aligned.m16n8k32.row.col.s32.s8.s8.s32 "
        "{%0,%1,%2,%3}, {%4,%5,%6,%7}, {%8,%9}, {%0,%1,%2,%3};\n"
        : "+r"(c[0]), "+r"(c[1]), "+r"(c[2]), "+r"(c[3])
        : "r"(a[0]), "r"(a[1]), "r"(a[2]), "r"(a[3]), "r"(b[0]), "r"(b[1]));
}
// quantize x (|x|<=s) to digits: t = rint(x*16256/s) = 128*q1 + q0
__device__ __forceinline__ void quant_dig(float x, float sc, int8_t& q1, int8_t& q0) {
    const float t = rintf(x * sc);
    const float f1 = rintf(t * (1.0f / 128.0f));
    q1 = (int8_t)(int)f1;
    q0 = (int8_t)(int)(t - 128.0f * f1);
}

// ===========================================================================
// GEMM: C[M,N] = act(A[M,K] @ Bt[N,K]^T + bias), int8 digit operands.
// ACT: 0 relu, 1 sigmoid.
// ===========================================================================
template <int ACT>
__global__ void __launch_bounds__(256, 1)
gemm_i8(const int8_t* __restrict__ A1, const int8_t* __restrict__ A0,
        const int8_t* __restrict__ B1, const int8_t* __restrict__ B0,
        const float* __restrict__ sA, const float* __restrict__ sB,
        const float* __restrict__ bias, float* __restrict__ C,
        int M, int N, int K)
{
    extern __shared__ char smem_raw[];
    const uint32_t sbase = (smem_u32(smem_raw) + 1023u) & ~1023u;
    const int tid = threadIdx.x, lane = tid & 31, warp = tid >> 5;
    const int wm = warp >> 1;            // 0..3 : M tiles of 32
    const int wn = warp & 1;             // 0..1 : N tiles of 64
    const long bm = (long)blockIdx.y * BM;
    const long bn = (long)blockIdx.x * BN;
    const int NC = K / BK;

    // ---- per-thread load geometry: 8 x 16B cp.async per stage ----
    const int lrow = tid >> 1;
    const int lch  = (tid & 1) * 2;
    const uint32_t so0 = tile_off(lrow, lch);
    const uint32_t so1 = tile_off(lrow, lch + 1);

    auto load_stage = [&](int c) {
        const uint32_t st = sbase + (c % STAGES) * STAGE_BYTES;
        const long kt = (long)c * BK;
        const long goA = (bm + lrow) * (long)K + kt + lch * 16;
        const long goB = (bn + lrow) * (long)K + kt + lch * 16;
        cpasync16(st + OFF_A1 + so0, A1 + goA);
        cpasync16(st + OFF_A1 + so1, A1 + goA + 16);
        cpasync16(st + OFF_A0 + so0, A0 + goA);
        cpasync16(st + OFF_A0 + so1, A0 + goA + 16);
        cpasync16(st + OFF_B1 + so0, B1 + goB);
        cpasync16(st + OFF_B1 + so1, B1 + goB + 16);
        cpasync16(st + OFF_B0 + so0, B0 + goB);
        cpasync16(st + OFF_B0 + so1, B0 + goB + 16);
        CP_COMMIT();
    };

    // ---- ldmatrix lane geometry ----
    const int a_rbase = wm * 32 + ((lane >> 3) & 1) * 8 + (lane & 7);
    const int b_rbase = wn * 64 + ((lane >> 3) & 1) * 8 + (lane & 7);
    const int ch_hi   = lane >> 4;   // 0/1: second 16B chunk of the k32 group

    int acc1[2][8][4];   // a1*b1 sums (scale 16384)
    int accm[2][8][4];   // a1*b0 + a0*b1 sums (scale 128)
#pragma unroll
    for (int mi = 0; mi < 2; mi++)
#pragma unroll
        for (int ni = 0; ni < 8; ni++)
#pragma unroll
            for (int j = 0; j < 4; j++) { acc1[mi][ni][j] = 0; accm[mi][ni][j] = 0; }

    auto compute = [&](int c) {
        const uint32_t st = sbase + (c % STAGES) * STAGE_BYTES;
#pragma unroll
        for (int kk = 0; kk < 2; kk++) {   // two k32 groups per BK=64
            uint32_t a1[2][4], a0[2][4];
#pragma unroll
            for (int mi = 0; mi < 2; mi++) {
                const uint32_t o = tile_off(a_rbase + mi * 16, kk * 2 + ch_hi);
                ldsm4(a1[mi][0], a1[mi][1], a1[mi][2], a1[mi][3], st + OFF_A1 + o);
                ldsm4(a0[mi][0], a0[mi][1], a0[mi][2], a0[mi][3], st + OFF_A0 + o);
            }
            uint32_t b1[8][2], b0[8][2];
#pragma unroll
            for (int nj = 0; nj < 4; nj++) {
                const uint32_t o = tile_off(b_rbase + nj * 16, kk * 2 + ch_hi);
                uint32_t t0, t1, t2, t3;
                ldsm4(t0, t1, t2, t3, st + OFF_B1 + o);
                b1[2 * nj][0] = t0; b1[2 * nj + 1][0] = t1;
                b1[2 * nj][1] = t2; b1[2 * nj + 1][1] = t3;
                ldsm4(t0, t1, t2, t3, st + OFF_B0 + o);
                b0[2 * nj][0] = t0; b0[2 * nj + 1][0] = t1;
                b0[2 * nj][1] = t2; b0[2 * nj + 1][1] = t3;
            }
#pragma unroll
            for (int mi = 0; mi < 2; mi++)
#pragma unroll
                for (int ni = 0; ni < 8; ni++) {
                    mma_s8(acc1[mi][ni], a1[mi], b1[ni]);   // hi*hi
                    mma_s8(accm[mi][ni], a1[mi], b0[ni]);   // hi*lo
                    mma_s8(accm[mi][ni], a0[mi], b1[ni]);   // lo*hi
                }
        }
    };

    load_stage(0); load_stage(1); load_stage(2);

    for (int c = 0; c < NC; c++) {
        CP_WAIT2();
        __syncthreads();
        compute(c);
        if (c + STAGES < NC) {
            __syncthreads();
            load_stage(c + STAGES);
        }
    }

    // ---- epilogue: rescale, bias, activation ----
    const float inv = 1.0f / (QSCALE * QSCALE);
    const int l4 = lane >> 2, l2 = (lane & 3) * 2;
#pragma unroll
    for (int mi = 0; mi < 2; mi++) {
        const long rg = bm + wm * 32 + mi * 16 + l4;
        const float sa0 = sA[rg] * inv;
        const float sa1 = sA[rg + 8] * inv;
#pragma unroll
        for (int ni = 0; ni < 8; ni++) {
            const long cg = bn + wn * 64 + ni * 8 + l2;
            const float sb0 = sB[cg], sb1 = sB[cg + 1];
            const float b0 = bias[cg], b1 = bias[cg + 1];
            const float f0 = 16384.0f * (float)acc1[mi][ni][0] + 128.0f * (float)accm[mi][ni][0];
            const float f1 = 16384.0f * (float)acc1[mi][ni][1] + 128.0f * (float)accm[mi][ni][1];
            const float f2 = 16384.0f * (float)acc1[mi][ni][2] + 128.0f * (float)accm[mi][ni][2];
            const float f3 = 16384.0f * (float)acc1[mi][ni][3] + 128.0f * (float)accm[mi][ni][3];
            float x0 = sa0 * sb0 * f0 + b0;
            float x1 = sa0 * sb1 * f1 + b1;
            float x2 = sa1 * sb0 * f2 + b0;
            float x3 = sa1 * sb1 * f3 + b1;
            if (ACT == 0) {
                x0 = fmaxf(x0, 0.f); x1 = fmaxf(x1, 0.f);
                x2 = fmaxf(x2, 0.f); x3 = fmaxf(x3, 0.f);
            } else {
                x0 = 1.f / (1.f + __expf(-x0));
                x1 = 1.f / (1.f + __expf(-x1));
                x2 = 1.f / (1.f + __expf(-x2));
                x3 = 1.f / (1.f + __expf(-x3));
            }
            *(float2*)&C[rg * (long)N + cg]       = make_float2(x0, x1);
            *(float2*)&C[(rg + 8) * (long)N + cg] = make_float2(x2, x3);
        }
    }
}

// ===========================================================================
// Column abs-max of W [K,N]: one block per 32 columns.
// ===========================================================================
__global__ void __launch_bounds__(256)
colmax_kernel(const float* __restrict__ W, float* __restrict__ s, int K, int N)
{
    __shared__ float red[256];
    const int col = blockIdx.x * 32 + (threadIdx.x & 31);
    const int r0 = threadIdx.x >> 5;
    float m = 1e-20f;
    for (int k = r0; k < K; k += 8)
        m = fmaxf(m, fabsf(W[(long)k * N + col]));
    red[threadIdx.x] = m;
    __syncthreads();
#pragma unroll
    for (int off = 128; off >= 32; off >>= 1) {
        if (threadIdx.x < off)
            red[threadIdx.x] = fmaxf(red[threadIdx.x], red[threadIdx.x + off]);
        __syncthreads();
    }
    if (threadIdx.x < 32) s[col] = red[threadIdx.x];
}

// ===========================================================================
// W [K,N] -> Wt digits [N,K] (transpose + quantize with per-col scale)
// ===========================================================================
__global__ void __launch_bounds__(256)
transpose_quant_kernel(const float* __restrict__ W, const float* __restrict__ s,
                       int8_t* __restrict__ Q1, int8_t* __restrict__ Q0,
                       int K, int N)
{
    __shared__ float t[32][33];
    const int tx = threadIdx.x, ty = threadIdx.y;
    const long n0 = (long)blockIdx.x * 32, k0 = (long)blockIdx.y * 32;
#pragma unroll
    for (int j = 0; j < 4; j++)
        t[ty + 8 * j][tx] = W[(k0 + ty + 8 * j) * N + n0 + tx];
    __syncthreads();
#pragma unroll
    for (int j = 0; j < 4; j++) {
        const long col = n0 + ty + 8 * j;
        const float sc = QSCALE / s[col];
        int8_t q1, q0;
        quant_dig(t[tx][ty + 8 * j], sc, q1, q0);
        const long o = col * K + k0 + tx;
        Q1[o] = q1;
        Q0[o] = q0;
    }
}

// ===========================================================================
// Per-row abs-max + quantize: x [rows, K] -> digits + scale. Block per row.
// ===========================================================================
__global__ void __launch_bounds__(256)
quant_rows_kernel(const float* __restrict__ x, int8_t* __restrict__ Q1,
                  int8_t* __restrict__ Q0, float* __restrict__ sa, int K)
{
    __shared__ float red[256];
    const long base = (long)blockIdx.x * K;
    const int tid = threadIdx.x;
    float m = 1e-20f;
    for (int i = tid; i < K; i += 256)
        m = fmaxf(m, fabsf(x[base + i]));
    red[tid] = m;
    __syncthreads();
#pragma unroll
    for (int off = 128; off > 0; off >>= 1) {
        if (tid < off) red[tid] = fmaxf(red[tid], red[tid + off]);
        __syncthreads();
    }
    const float s = red[0];
    const float sc = QSCALE / s;
    for (int i = tid; i < K; i += 256) {
        int8_t q1, q0;
        quant_dig(x[base + i], sc, q1, q0);
        Q1[base + i] = q1;
        Q0[base + i] = q0;
    }
    if (tid == 0) sa[blockIdx.x] = s;
}

// ===========================================================================
// Exact per-row top-64 keep (radix select, nonneg) + int8 digit output
// ===========================================================================
__global__ void __launch_bounds__(256)
topk64_quant_kernel(const float* __restrict__ h, int8_t* __restrict__ Q1,
                    int8_t* __restrict__ Q0, float* __restrict__ sa)
{
    __shared__ float vals[1024];
    __shared__ int hist[256];
    __shared__ float redm[256];
    __shared__ int s_k;
    __shared__ unsigned s_prefix;

    const float* row = h + (long)blockIdx.x * 1024;
    const int tid = threadIdx.x;

    float m = 1e-20f;
#pragma unroll
    for (int i = tid; i < 1024; i += 256) {
        const float v = row[i];
        vals[i] = v;
        m = fmaxf(m, v);
    }
    redm[tid] = m;
    if (tid == 0) { s_k = 64; s_prefix = 0u; }
    __syncthreads();
#pragma unroll
    for (int off = 128; off > 0; off >>= 1) {
        if (tid < off) redm[tid] = fmaxf(redm[tid], redm[tid + off]);
        __syncthreads();
    }
    const float smax = redm[0];

#pragma unroll
    for (int shift = 24; shift >= 0; shift -= 8) {
        hist[tid] = 0;
        __syncthreads();
        const unsigned hmask = (shift == 24) ? 0u : (0xFFFFFFFFu << (shift + 8));
        const unsigned pfx = s_prefix;
#pragma unroll
        for (int i = tid; i < 1024; i += 256) {
            const unsigned u = __float_as_uint(vals[i]);
            if ((u & hmask) == pfx)
                atomicAdd(&hist[(u >> shift) & 255], 1);
        }
        __syncthreads();
        if (tid == 0) {
            int k = s_k, cum = 0, d;
            for (d = 255; d > 0; d--) {
                const int c = hist[d];
                if (cum + c >= k) break;
                cum += c;
            }
            s_prefix = pfx | ((unsigned)d << shift);
            s_k = k - cum;
        }
        __syncthreads();
    }

    const float thr = __uint_as_float(s_prefix);
    const float sc = QSCALE / smax;
    const long base = (long)blockIdx.x * 1024;
#pragma unroll
    for (int i = tid; i < 1024; i += 256) {
        const float v = vals[i];
        const float kept = (v >= thr) ? v : 0.0f;
        int8_t q1, q0;
        quant_dig(kept, sc, q1, q0);
        Q1[base + i] = q1;
        Q0[base + i] = q0;
    }
    if (tid == 0) sa[blockIdx.x] = smax;
}

// ===========================================================================
extern "C" void kernel_launch(void* const* d_in, const int* in_sizes, int n_in,
                              void* d_out, int out_size)
{
    const float* X   = (const float*)d_in[0];   // [4096, 12288]
    const float* We1 = (const float*)d_in[1];   // [12288, 1024]
    const float* be1 = (const float*)d_in[2];
    const float* Wd1 = (const float*)d_in[3];   // [1024, 1024]
    const float* bd1 = (const float*)d_in[4];
    const float* Wd2 = (const float*)d_in[5];   // [1024, 12288]
    const float* bd2 = (const float*)d_in[6];
    float* out = (float*)d_out;                 // [4096, 12288]

    int8_t *X1, *X0, *W1q1, *W1q0, *W2q1, *W2q0, *W3q1, *W3q0, *h1, *h0, *d1, *d0;
    float *h, *d, *sX, *sh, *sd, *sW1, *sW2, *sW3;
    cudaGetSymbolAddress((void**)&X1, g_X1);     cudaGetSymbolAddress((void**)&X0, g_X0);
    cudaGetSymbolAddress((void**)&W1q1, g_W1q1); cudaGetSymbolAddress((void**)&W1q0, g_W1q0);
    cudaGetSymbolAddress((void**)&W2q1, g_W2q1); cudaGetSymbolAddress((void**)&W2q0, g_W2q0);
    cudaGetSymbolAddress((void**)&W3q1, g_W3q1); cudaGetSymbolAddress((void**)&W3q0, g_W3q0);
    cudaGetSymbolAddress((void**)&h1, g_h1);     cudaGetSymbolAddress((void**)&h0, g_h0);
    cudaGetSymbolAddress((void**)&d1, g_d1);     cudaGetSymbolAddress((void**)&d0, g_d0);
    cudaGetSymbolAddress((void**)&h, g_h);       cudaGetSymbolAddress((void**)&d, g_d);
    cudaGetSymbolAddress((void**)&sX, g_sX);     cudaGetSymbolAddress((void**)&sh, g_sh);
    cudaGetSymbolAddress((void**)&sd, g_sd);
    cudaGetSymbolAddress((void**)&sW1, g_sW1);   cudaGetSymbolAddress((void**)&sW2, g_sW2);
    cudaGetSymbolAddress((void**)&sW3, g_sW3);

    cudaFuncSetAttribute(gemm_i8<0>, cudaFuncAttributeMaxDynamicSharedMemorySize, SMEM_ALLOC);
    cudaFuncSetAttribute(gemm_i8<1>, cudaFuncAttributeMaxDynamicSharedMemorySize, SMEM_ALLOC);

    const int M = 4096, HID = 1024, D = 12288;

    // ---- operand prep: column scales, transpose+quant weights, quant X ----
    colmax_kernel<<<HID / 32, 256>>>(We1, sW1, D, HID);
    colmax_kernel<<<HID / 32, 256>>>(Wd1, sW2, HID, HID);
    colmax_kernel<<<D / 32, 256>>>(Wd2, sW3, HID, D);
    transpose_quant_kernel<<<dim3(HID / 32, D / 32), dim3(32, 8)>>>(We1, sW1, W1q1, W1q0, D, HID);
    transpose_quant_kernel<<<dim3(HID / 32, HID / 32), dim3(32, 8)>>>(Wd1, sW2, W2q1, W2q0, HID, HID);
    transpose_quant_kernel<<<dim3(D / 32, HID / 32), dim3(32, 8)>>>(Wd2, sW3, W3q1, W3q0, HID, D);
    quant_rows_kernel<<<M, 256>>>(X, X1, X0, sX, D);

    // ---- layer 1: h = relu(X @ We1 + be1) ----
    gemm_i8<0><<<dim3(HID / BN, M / BM), 256, SMEM_ALLOC>>>(
        X1, X0, W1q1, W1q0, sX, sW1, be1, h, M, HID, D);
    // ---- top-64 keep + quantize ----
    topk64_quant_kernel<<<M, 256>>>(h, h1, h0, sh);
    // ---- layer 2: d = relu(h @ Wd1 + bd1) ----
    gemm_i8<0><<<dim3(HID / BN, M / BM), 256, SMEM_ALLOC>>>(
        h1, h0, W2q1, W2q0, sh, sW2, bd1, d, M, HID, HID);
    quant_rows_kernel<<<M, 256>>>(d, d1, d0, sd, HID);
    // ---- layer 3: out = sigmoid(d @ Wd2 + bd2) ----
    gemm_i8<1><<<dim3(D / BN, M / BM), 256, SMEM_ALLOC>>>(
        d1, d0, W3q1, W3q0, sd, sW3, bd2, out, M, D, HID);
}

// round 9
// speedup vs baseline: 1.7421x; 1.1854x over previous
#include <cuda_runtime.h>
#include <cstdint>

// ===========================================================================
// DenseAE: out = sigmoid(relu(ksparse64(relu(X@We1+be1))@Wd1+bd1)@Wd2+bd2)
// B=4096, D=12288, HID=1024, k=64
// R9: int8 digit-split GEMMs (numerics proven in R7) with
//  - 512 threads / 16 warps per CTA (warp tile 32x32)
//  - 4-stage pipeline, single __syncthreads per chunk, load(c+3) into the
//    slot freed at c-1 (fixes R8's same-slot write race).
// ===========================================================================

#define BM 128
#define BN 128
#define BK 64
#define STAGES 4
#define STAGE_BYTES 32768
#define OFF_A1 0
#define OFF_A0 8192
#define OFF_B1 16384
#define OFF_B0 24576
#define SMEM_ALLOC (STAGES * STAGE_BYTES + 1024)
#define NTHREADS 512

#define QSCALE 16256.0f   // 127*128: a1 in [-127,127], a0 in [-64,64]

// ---------------- scratch (device globals; no runtime allocation) ----------
__device__ __align__(128) int8_t g_X1[4096L * 12288];
__device__ __align__(128) int8_t g_X0[4096L * 12288];
__device__ __align__(128) int8_t g_W1q1[1024L * 12288];  // We1^T digits
__device__ __align__(128) int8_t g_W1q0[1024L * 12288];
__device__ __align__(128) int8_t g_W2q1[1024L * 1024];   // Wd1^T digits
__device__ __align__(128) int8_t g_W2q0[1024L * 1024];
__device__ __align__(128) int8_t g_W3q1[12288L * 1024];  // Wd2^T digits
__device__ __align__(128) int8_t g_W3q0[12288L * 1024];
__device__ float g_h[4096L * 1024];
__device__ float g_d[4096L * 1024];
__device__ __align__(128) int8_t g_h1[4096L * 1024];
__device__ __align__(128) int8_t g_h0[4096L * 1024];
__device__ __align__(128) int8_t g_d1[4096L * 1024];
__device__ __align__(128) int8_t g_d0[4096L * 1024];
__device__ float g_sX[4096];
__device__ float g_sh[4096];
__device__ float g_sd[4096];
__device__ float g_sW1[1024];
__device__ float g_sW2[1024];
__device__ float g_sW3[12288];

// ---------------- helpers ---------------------------------------------------
__device__ __forceinline__ uint32_t smem_u32(const void* p) {
    uint32_t a;
    asm("{ .reg .u64 t; cvta.to.shared.u64 t, %1; cvt.u32.u64 %0, t; }" : "=r"(a) : "l"(p));
    return a;
}
__device__ __forceinline__ void cpasync16(uint32_t dst, const void* src) {
    asm volatile("cp.async.cg.shared.global [%0], [%1], 16;" :: "r"(dst), "l"(src));
}
#define CP_COMMIT() asm volatile("cp.async.commit_group;")
#define CP_WAIT2()  asm volatile("cp.async.wait_group 2;")

// [128 rows x 64B] tile; row pairs share a 128B line; 16B chunks XOR-swizzled.
__device__ __forceinline__ uint32_t tile_off(int row, int ch) {
    const int line = row >> 1;
    const int idx = ((row & 1) << 2) | ch;
    return (uint32_t)((line << 7) + ((idx ^ (line & 7)) << 4));
}

__device__ __forceinline__ void ldsm4(uint32_t& r0, uint32_t& r1, uint32_t& r2,
                                      uint32_t& r3, uint32_t a) {
    asm volatile("ldmatrix.sync.aligned.m8n8.x4.shared.b16 {%0,%1,%2,%3}, [%4];"
                 : "=r"(r0), "=r"(r1), "=r"(r2), "=r"(r3) : "r"(a));
}
__device__ __forceinline__ void mma_s8(int c[4], const uint32_t a[4],
                                       const uint32_t b[2]) {
    asm volatile(
        "mma.sync.aligned.m16n8k32.row.col.s32.s8.s8.s32 "
        "{%0,%1,%2,%3}, {%4,%5,%6,%7}, {%8,%9}, {%0,%1,%2,%3};\n"
        : "+r"(c[0]), "+r"(c[1]), "+r"(c[2]), "+r"(c[3])
        : "r"(a[0]), "r"(a[1]), "r"(a[2]), "r"(a[3]), "r"(b[0]), "r"(b[1]));
}
// quantize x (|x|<=s) to digits: t = rint(x*16256/s) = 128*q1 + q0
__device__ __forceinline__ void quant_dig(float x, float sc, int8_t& q1, int8_t& q0) {
    const float t = rintf(x * sc);
    const float f1 = rintf(t * (1.0f / 128.0f));
    q1 = (int8_t)(int)f1;
    q0 = (int8_t)(int)(t - 128.0f * f1);
}

// ===========================================================================
// GEMM: C[M,N] = act(A[M,K] @ Bt[N,K]^T + bias), int8 digit operands.
// ACT: 0 relu, 1 sigmoid. 512 threads, warp grid 4x4, warp tile 32x32.
// ===========================================================================
template <int ACT>
__global__ void __launch_bounds__(NTHREADS, 1)
gemm_i8(const int8_t* __restrict__ A1, const int8_t* __restrict__ A0,
        const int8_t* __restrict__ B1, const int8_t* __restrict__ B0,
        const float* __restrict__ sA, const float* __restrict__ sB,
        const float* __restrict__ bias, float* __restrict__ C,
        int M, int N, int K)
{
    extern __shared__ char smem_raw[];
    const uint32_t sbase = (smem_u32(smem_raw) + 1023u) & ~1023u;
    const int tid = threadIdx.x, lane = tid & 31, warp = tid >> 5;
    const int wm = warp >> 2;            // 0..3 : M tiles of 32
    const int wn = warp & 3;             // 0..3 : N tiles of 32
    const long bm = (long)blockIdx.y * BM;
    const long bn = (long)blockIdx.x * BN;
    const int NC = K / BK;

    // ---- per-thread load geometry: 1 x 16B cp.async per array per stage ----
    const int lrow = tid >> 2;           // 0..127
    const int lch  = tid & 3;            // 0..3
    const uint32_t so = tile_off(lrow, lch);

    auto load_stage = [&](int c) {
        const uint32_t st = sbase + (c % STAGES) * STAGE_BYTES;
        const long kt = (long)c * BK;
        const long goA = (bm + lrow) * (long)K + kt + lch * 16;
        const long goB = (bn + lrow) * (long)K + kt + lch * 16;
        cpasync16(st + OFF_A1 + so, A1 + goA);
        cpasync16(st + OFF_A0 + so, A0 + goA);
        cpasync16(st + OFF_B1 + so, B1 + goB);
        cpasync16(st + OFF_B0 + so, B0 + goB);
        CP_COMMIT();
    };

    // ---- ldmatrix lane geometry ----
    const int a_rbase = wm * 32 + ((lane >> 3) & 1) * 8 + (lane & 7);
    const int b_rbase = wn * 32 + ((lane >> 3) & 1) * 8 + (lane & 7);
    const int ch_hi   = lane >> 4;   // 0/1: second 16B chunk of the k32 group

    int acc1[2][4][4];   // a1*b1 sums (scale 16384)
    int accm[2][4][4];   // a1*b0 + a0*b1 sums (scale 128)
#pragma unroll
    for (int mi = 0; mi < 2; mi++)
#pragma unroll
        for (int ni = 0; ni < 4; ni++)
#pragma unroll
            for (int j = 0; j < 4; j++) { acc1[mi][ni][j] = 0; accm[mi][ni][j] = 0; }

    auto compute = [&](int c) {
        const uint32_t st = sbase + (c % STAGES) * STAGE_BYTES;
#pragma unroll
        for (int kk = 0; kk < 2; kk++) {   // two k32 groups per BK=64
            uint32_t a1[2][4], a0[2][4];
#pragma unroll
            for (int mi = 0; mi < 2; mi++) {
                const uint32_t o = tile_off(a_rbase + mi * 16, kk * 2 + ch_hi);
                ldsm4(a1[mi][0], a1[mi][1], a1[mi][2], a1[mi][3], st + OFF_A1 + o);
                ldsm4(a0[mi][0], a0[mi][1], a0[mi][2], a0[mi][3], st + OFF_A0 + o);
            }
            uint32_t b1[4][2], b0[4][2];
#pragma unroll
            for (int nj = 0; nj < 2; nj++) {
                const uint32_t o = tile_off(b_rbase + nj * 16, kk * 2 + ch_hi);
                uint32_t t0, t1, t2, t3;
                ldsm4(t0, t1, t2, t3, st + OFF_B1 + o);
                b1[2 * nj][0] = t0; b1[2 * nj + 1][0] = t1;
                b1[2 * nj][1] = t2; b1[2 * nj + 1][1] = t3;
                ldsm4(t0, t1, t2, t3, st + OFF_B0 + o);
                b0[2 * nj][0] = t0; b0[2 * nj + 1][0] = t1;
                b0[2 * nj][1] = t2; b0[2 * nj + 1][1] = t3;
            }
#pragma unroll
            for (int mi = 0; mi < 2; mi++)
#pragma unroll
                for (int ni = 0; ni < 4; ni++) {
                    mma_s8(acc1[mi][ni], a1[mi], b1[ni]);   // hi*hi
                    mma_s8(accm[mi][ni], a1[mi], b0[ni]);   // hi*lo
                    mma_s8(accm[mi][ni], a0[mi], b1[ni]);   // lo*hi
                }
        }
    };

    // ---- prologue: fill 3 of 4 stages ----
    load_stage(0); load_stage(1); load_stage(2);

    for (int c = 0; c < NC; c++) {
        CP_WAIT2();                 // stage c complete (3+c groups committed)
        __syncthreads();            // data visible; slot (c-1)%4 fully consumed
        if (c + STAGES - 1 < NC) load_stage(c + STAGES - 1);  // -> slot (c-1)%4
        else                     CP_COMMIT();   // keep group accounting exact
        compute(c);
    }

    // ---- epilogue: rescale, bias, activation ----
    const float inv = 1.0f / (QSCALE * QSCALE);
    const int l4 = lane >> 2, l2 = (lane & 3) * 2;
#pragma unroll
    for (int mi = 0; mi < 2; mi++) {
        const long rg = bm + wm * 32 + mi * 16 + l4;
        const float sa0 = sA[rg] * inv;
        const float sa1 = sA[rg + 8] * inv;
#pragma unroll
        for (int ni = 0; ni < 4; ni++) {
            const long cg = bn + wn * 32 + ni * 8 + l2;
            const float sb0 = sB[cg], sb1 = sB[cg + 1];
            const float b0 = bias[cg], b1 = bias[cg + 1];
            const float f0 = 16384.0f * (float)acc1[mi][ni][0] + 128.0f * (float)accm[mi][ni][0];
            const float f1 = 16384.0f * (float)acc1[mi][ni][1] + 128.0f * (float)accm[mi][ni][1];
            const float f2 = 16384.0f * (float)acc1[mi][ni][2] + 128.0f * (float)accm[mi][ni][2];
            const float f3 = 16384.0f * (float)acc1[mi][ni][3] + 128.0f * (float)accm[mi][ni][3];
            float x0 = sa0 * sb0 * f0 + b0;
            float x1 = sa0 * sb1 * f1 + b1;
            float x2 = sa1 * sb0 * f2 + b0;
            float x3 = sa1 * sb1 * f3 + b1;
            if (ACT == 0) {
                x0 = fmaxf(x0, 0.f); x1 = fmaxf(x1, 0.f);
                x2 = fmaxf(x2, 0.f); x3 = fmaxf(x3, 0.f);
            } else {
                x0 = 1.f / (1.f + __expf(-x0));
                x1 = 1.f / (1.f + __expf(-x1));
                x2 = 1.f / (1.f + __expf(-x2));
                x3 = 1.f / (1.f + __expf(-x3));
            }
            *(float2*)&C[rg * (long)N + cg]       = make_float2(x0, x1);
            *(float2*)&C[(rg + 8) * (long)N + cg] = make_float2(x2, x3);
        }
    }
}

// ===========================================================================
// Column abs-max of W [K,N]: one block per 32 columns.
// ===========================================================================
__global__ void __launch_bounds__(256)
colmax_kernel(const float* __restrict__ W, float* __restrict__ s, int K, int N)
{
    __shared__ float red[256];
    const int col = blockIdx.x * 32 + (threadIdx.x & 31);
    const int r0 = threadIdx.x >> 5;
    float m = 1e-20f;
    for (int k = r0; k < K; k += 8)
        m = fmaxf(m, fabsf(W[(long)k * N + col]));
    red[threadIdx.x] = m;
    __syncthreads();
#pragma unroll
    for (int off = 128; off >= 32; off >>= 1) {
        if (threadIdx.x < off)
            red[threadIdx.x] = fmaxf(red[threadIdx.x], red[threadIdx.x + off]);
        __syncthreads();
    }
    if (threadIdx.x < 32) s[col] = red[threadIdx.x];
}

// ===========================================================================
// W [K,N] -> Wt digits [N,K] (transpose + quantize with per-col scale)
// ===========================================================================
__global__ void __launch_bounds__(256)
transpose_quant_kernel(const float* __restrict__ W, const float* __restrict__ s,
                       int8_t* __restrict__ Q1, int8_t* __restrict__ Q0,
                       int K, int N)
{
    __shared__ float t[32][33];
    const int tx = threadIdx.x, ty = threadIdx.y;
    const long n0 = (long)blockIdx.x * 32, k0 = (long)blockIdx.y * 32;
#pragma unroll
    for (int j = 0; j < 4; j++)
        t[ty + 8 * j][tx] = W[(k0 + ty + 8 * j) * N + n0 + tx];
    __syncthreads();
#pragma unroll
    for (int j = 0; j < 4; j++) {
        const long col = n0 + ty + 8 * j;
        const float sc = QSCALE / s[col];
        int8_t q1, q0;
        quant_dig(t[tx][ty + 8 * j], sc, q1, q0);
        const long o = col * K + k0 + tx;
        Q1[o] = q1;
        Q0[o] = q0;
    }
}

// ===========================================================================
// Per-row abs-max + quantize: x [rows, K] -> digits + scale. Block per row.
// ===========================================================================
__global__ void __launch_bounds__(256)
quant_rows_kernel(const float* __restrict__ x, int8_t* __restrict__ Q1,
                  int8_t* __restrict__ Q0, float* __restrict__ sa, int K)
{
    __shared__ float red[256];
    const long base = (long)blockIdx.x * K;
    const int tid = threadIdx.x;
    float m = 1e-20f;
    for (int i = tid; i < K; i += 256)
        m = fmaxf(m, fabsf(x[base + i]));
    red[tid] = m;
    __syncthreads();
#pragma unroll
    for (int off = 128; off > 0; off >>= 1) {
        if (tid < off) red[tid] = fmaxf(red[tid], red[tid + off]);
        __syncthreads();
    }
    const float s = red[0];
    const float sc = QSCALE / s;
    for (int i = tid; i < K; i += 256) {
        int8_t q1, q0;
        quant_dig(x[base + i], sc, q1, q0);
        Q1[base + i] = q1;
        Q0[base + i] = q0;
    }
    if (tid == 0) sa[blockIdx.x] = s;
}

// ===========================================================================
// Exact per-row top-64 keep (radix select, nonneg) + int8 digit output
// ===========================================================================
__global__ void __launch_bounds__(256)
topk64_quant_kernel(const float* __restrict__ h, int8_t* __restrict__ Q1,
                    int8_t* __restrict__ Q0, float* __restrict__ sa)
{
    __shared__ float vals[1024];
    __shared__ int hist[256];
    __shared__ float redm[256];
    __shared__ int s_k;
    __shared__ unsigned s_prefix;

    const float* row = h + (long)blockIdx.x * 1024;
    const int tid = threadIdx.x;

    float m = 1e-20f;
#pragma unroll
    for (int i = tid; i < 1024; i += 256) {
        const float v = row[i];
        vals[i] = v;
        m = fmaxf(m, v);
    }
    redm[tid] = m;
    if (tid == 0) { s_k = 64; s_prefix = 0u; }
    __syncthreads();
#pragma unroll
    for (int off = 128; off > 0; off >>= 1) {
        if (tid < off) redm[tid] = fmaxf(redm[tid], redm[tid + off]);
        __syncthreads();
    }
    const float smax = redm[0];

#pragma unroll
    for (int shift = 24; shift >= 0; shift -= 8) {
        hist[tid] = 0;
        __syncthreads();
        const unsigned hmask = (shift == 24) ? 0u : (0xFFFFFFFFu << (shift + 8));
        const unsigned pfx = s_prefix;
#pragma unroll
        for (int i = tid; i < 1024; i += 256) {
            const unsigned u = __float_as_uint(vals[i]);
            if ((u & hmask) == pfx)
                atomicAdd(&hist[(u >> shift) & 255], 1);
        }
        __syncthreads();
        if (tid == 0) {
            int k = s_k, cum = 0, d;
            for (d = 255; d > 0; d--) {
                const int c = hist[d];
                if (cum + c >= k) break;
                cum += c;
            }
            s_prefix = pfx | ((unsigned)d << shift);
            s_k = k - cum;
        }
        __syncthreads();
    }

    const float thr = __uint_as_float(s_prefix);
    const float sc = QSCALE / smax;
    const long base = (long)blockIdx.x * 1024;
#pragma unroll
    for (int i = tid; i < 1024; i += 256) {
        const float v = vals[i];
        const float kept = (v >= thr) ? v : 0.0f;
        int8_t q1, q0;
        quant_dig(kept, sc, q1, q0);
        Q1[base + i] = q1;
        Q0[base + i] = q0;
    }
    if (tid == 0) sa[blockIdx.x] = smax;
}

// ===========================================================================
extern "C" void kernel_launch(void* const* d_in, const int* in_sizes, int n_in,
                              void* d_out, int out_size)
{
    const float* X   = (const float*)d_in[0];   // [4096, 12288]
    const float* We1 = (const float*)d_in[1];   // [12288, 1024]
    const float* be1 = (const float*)d_in[2];
    const float* Wd1 = (const float*)d_in[3];   // [1024, 1024]
    const float* bd1 = (const float*)d_in[4];
    const float* Wd2 = (const float*)d_in[5];   // [1024, 12288]
    const float* bd2 = (const float*)d_in[6];
    float* out = (float*)d_out;                 // [4096, 12288]

    int8_t *X1, *X0, *W1q1, *W1q0, *W2q1, *W2q0, *W3q1, *W3q0, *h1, *h0, *d1, *d0;
    float *h, *d, *sX, *sh, *sd, *sW1, *sW2, *sW3;
    cudaGetSymbolAddress((void**)&X1, g_X1);     cudaGetSymbolAddress((void**)&X0, g_X0);
    cudaGetSymbolAddress((void**)&W1q1, g_W1q1); cudaGetSymbolAddress((void**)&W1q0, g_W1q0);
    cudaGetSymbolAddress((void**)&W2q1, g_W2q1); cudaGetSymbolAddress((void**)&W2q0, g_W2q0);
    cudaGetSymbolAddress((void**)&W3q1, g_W3q1); cudaGetSymbolAddress((void**)&W3q0, g_W3q0);
    cudaGetSymbolAddress((void**)&h1, g_h1);     cudaGetSymbolAddress((void**)&h0, g_h0);
    cudaGetSymbolAddress((void**)&d1, g_d1);     cudaGetSymbolAddress((void**)&d0, g_d0);
    cudaGetSymbolAddress((void**)&h, g_h);       cudaGetSymbolAddress((void**)&d, g_d);
    cudaGetSymbolAddress((void**)&sX, g_sX);     cudaGetSymbolAddress((void**)&sh, g_sh);
    cudaGetSymbolAddress((void**)&sd, g_sd);
    cudaGetSymbolAddress((void**)&sW1, g_sW1);   cudaGetSymbolAddress((void**)&sW2, g_sW2);
    cudaGetSymbolAddress((void**)&sW3, g_sW3);

    cudaFuncSetAttribute(gemm_i8<0>, cudaFuncAttributeMaxDynamicSharedMemorySize, SMEM_ALLOC);
    cudaFuncSetAttribute(gemm_i8<1>, cudaFuncAttributeMaxDynamicSharedMemorySize, SMEM_ALLOC);

    const int M = 4096, HID = 1024, D = 12288;

    // ---- operand prep: column scales, transpose+quant weights, quant X ----
    colmax_kernel<<<HID / 32, 256>>>(We1, sW1, D, HID);
    colmax_kernel<<<HID / 32, 256>>>(Wd1, sW2, HID, HID);
    colmax_kernel<<<D / 32, 256>>>(Wd2, sW3, HID, D);
    transpose_quant_kernel<<<dim3(HID / 32, D / 32), dim3(32, 8)>>>(We1, sW1, W1q1, W1q0, D, HID);
    transpose_quant_kernel<<<dim3(HID / 32, HID / 32), dim3(32, 8)>>>(Wd1, sW2, W2q1, W2q0, HID, HID);
    transpose_quant_kernel<<<dim3(D / 32, HID / 32), dim3(32, 8)>>>(Wd2, sW3, W3q1, W3q0, HID, D);
    quant_rows_kernel<<<M, 256>>>(X, X1, X0, sX, D);

    // ---- layer 1: h = relu(X @ We1 + be1) ----
    gemm_i8<0><<<dim3(HID / BN, M / BM), NTHREADS, SMEM_ALLOC>>>(
        X1, X0, W1q1, W1q0, sX, sW1, be1, h, M, HID, D);
    // ---- top-64 keep + quantize ----
    topk64_quant_kernel<<<M, 256>>>(h, h1, h0, sh);
    // ---- layer 2: d = relu(h @ Wd1 + bd1) ----
    gemm_i8<0><<<dim3(HID / BN, M / BM), NTHREADS, SMEM_ALLOC>>>(
        h1, h0, W2q1, W2q0, sh, sW2, bd1, d, M, HID, HID);
    quant_rows_kernel<<<M, 256>>>(d, d1, d0, sd, HID);
    // ---- layer 3: out = sigmoid(d @ Wd2 + bd2) ----
    gemm_i8<1><<<dim3(D / BN, M / BM), NTHREADS, SMEM_ALLOC>>>(
        d1, d0, W3q1, W3q0, sd, sW3, bd2, out, M, D, HID);
}

// round 10
// speedup vs baseline: 1.8620x; 1.0689x over previous
#include <cuda_runtime.h>
#include <cstdint>

// ===========================================================================
// DenseAE: out = sigmoid(relu(ksparse64(relu(X@We1+be1))@Wd1+bd1)@Wd2+bd2)
// B=4096, D=12288, HID=1024, k=64
// R10: R9 GEMMs (at legacy-mma tensor ceiling) + prep overhaul:
//  - colmax: split-K atomicMax, coalesced, well-parallelized
//  - quant_rows: smem row cache (single DRAM read), packed char4 writes
//  - transpose_quant: 64x32 tiles, 8B packed digit stores
// ===========================================================================

#define BM 128
#define BN 128
#define BK 64
#define STAGES 4
#define STAGE_BYTES 32768
#define OFF_A1 0
#define OFF_A0 8192
#define OFF_B1 16384
#define OFF_B0 24576
#define SMEM_ALLOC (STAGES * STAGE_BYTES + 1024)
#define NTHREADS 512

#define QSCALE 16256.0f   // 127*128: a1 in [-127,127], a0 in [-64,64]

// ---------------- scratch (device globals; no runtime allocation) ----------
__device__ __align__(128) int8_t g_X1[4096L * 12288];
__device__ __align__(128) int8_t g_X0[4096L * 12288];
__device__ __align__(128) int8_t g_W1q1[1024L * 12288];  // We1^T digits
__device__ __align__(128) int8_t g_W1q0[1024L * 12288];
__device__ __align__(128) int8_t g_W2q1[1024L * 1024];   // Wd1^T digits
__device__ __align__(128) int8_t g_W2q0[1024L * 1024];
__device__ __align__(128) int8_t g_W3q1[12288L * 1024];  // Wd2^T digits
__device__ __align__(128) int8_t g_W3q0[12288L * 1024];
__device__ float g_h[4096L * 1024];
__device__ float g_d[4096L * 1024];
__device__ __align__(128) int8_t g_h1[4096L * 1024];
__device__ __align__(128) int8_t g_h0[4096L * 1024];
__device__ __align__(128) int8_t g_d1[4096L * 1024];
__device__ __align__(128) int8_t g_d0[4096L * 1024];
__device__ float g_sX[4096];
__device__ float g_sh[4096];
__device__ float g_sd[4096];
__device__ float g_sW1[1024];   // written via atomicMax on uint bits (idempotent)
__device__ float g_sW2[1024];
__device__ float g_sW3[12288];

// ---------------- helpers ---------------------------------------------------
__device__ __forceinline__ uint32_t smem_u32(const void* p) {
    uint32_t a;
    asm("{ .reg .u64 t; cvta.to.shared.u64 t, %1; cvt.u32.u64 %0, t; }" : "=r"(a) : "l"(p));
    return a;
}
__device__ __forceinline__ void cpasync16(uint32_t dst, const void* src) {
    asm volatile("cp.async.cg.shared.global [%0], [%1], 16;" :: "r"(dst), "l"(src));
}
#define CP_COMMIT() asm volatile("cp.async.commit_group;")
#define CP_WAIT2()  asm volatile("cp.async.wait_group 2;")

// [128 rows x 64B] tile; row pairs share a 128B line; 16B chunks XOR-swizzled.
__device__ __forceinline__ uint32_t tile_off(int row, int ch) {
    const int line = row >> 1;
    const int idx = ((row & 1) << 2) | ch;
    return (uint32_t)((line << 7) + ((idx ^ (line & 7)) << 4));
}

__device__ __forceinline__ void ldsm4(uint32_t& r0, uint32_t& r1, uint32_t& r2,
                                      uint32_t& r3, uint32_t a) {
    asm volatile("ldmatrix.sync.aligned.m8n8.x4.shared.b16 {%0,%1,%2,%3}, [%4];"
                 : "=r"(r0), "=r"(r1), "=r"(r2), "=r"(r3) : "r"(a));
}
__device__ __forceinline__ void mma_s8(int c[4], const uint32_t a[4],
                                       const uint32_t b[2]) {
    asm volatile(
        "mma.sync.aligned.m16n8k32.row.col.s32.s8.s8.s32 "
        "{%0,%1,%2,%3}, {%4,%5,%6,%7}, {%8,%9}, {%0,%1,%2,%3};\n"
        : "+r"(c[0]), "+r"(c[1]), "+r"(c[2]), "+r"(c[3])
        : "r"(a[0]), "r"(a[1]), "r"(a[2]), "r"(a[3]), "r"(b[0]), "r"(b[1]));
}
// quantize x (|x|<=s) to digits: t = rint(x*16256/s) = 128*q1 + q0
__device__ __forceinline__ void quant_dig(float x, float sc, int8_t& q1, int8_t& q0) {
    const float t = rintf(x * sc);
    const float f1 = rintf(t * (1.0f / 128.0f));
    q1 = (int8_t)(int)f1;
    q0 = (int8_t)(int)(t - 128.0f * f1);
}
__device__ __forceinline__ uint32_t pack4(int8_t a, int8_t b, int8_t c, int8_t d) {
    return (uint32_t)(uint8_t)a | ((uint32_t)(uint8_t)b << 8) |
           ((uint32_t)(uint8_t)c << 16) | ((uint32_t)(uint8_t)d << 24);
}

// ===========================================================================
// GEMM: C[M,N] = act(A[M,K] @ Bt[N,K]^T + bias), int8 digit operands.
// (unchanged from R9 — passing at rel_err 4.35e-4, ~95% of legacy ceiling)
// ===========================================================================
template <int ACT>
__global__ void __launch_bounds__(NTHREADS, 1)
gemm_i8(const int8_t* __restrict__ A1, const int8_t* __restrict__ A0,
        const int8_t* __restrict__ B1, const int8_t* __restrict__ B0,
        const float* __restrict__ sA, const float* __restrict__ sB,
        const float* __restrict__ bias, float* __restrict__ C,
        int M, int N, int K)
{
    extern __shared__ char smem_raw[];
    const uint32_t sbase = (smem_u32(smem_raw) + 1023u) & ~1023u;
    const int tid = threadIdx.x, lane = tid & 31, warp = tid >> 5;
    const int wm = warp >> 2;            // 0..3 : M tiles of 32
    const int wn = warp & 3;             // 0..3 : N tiles of 32
    const long bm = (long)blockIdx.y * BM;
    const long bn = (long)blockIdx.x * BN;
    const int NC = K / BK;

    const int lrow = tid >> 2;           // 0..127
    const int lch  = tid & 3;            // 0..3
    const uint32_t so = tile_off(lrow, lch);

    auto load_stage = [&](int c) {
        const uint32_t st = sbase + (c % STAGES) * STAGE_BYTES;
        const long kt = (long)c * BK;
        const long goA = (bm + lrow) * (long)K + kt + lch * 16;
        const long goB = (bn + lrow) * (long)K + kt + lch * 16;
        cpasync16(st + OFF_A1 + so, A1 + goA);
        cpasync16(st + OFF_A0 + so, A0 + goA);
        cpasync16(st + OFF_B1 + so, B1 + goB);
        cpasync16(st + OFF_B0 + so, B0 + goB);
        CP_COMMIT();
    };

    const int a_rbase = wm * 32 + ((lane >> 3) & 1) * 8 + (lane & 7);
    const int b_rbase = wn * 32 + ((lane >> 3) & 1) * 8 + (lane & 7);
    const int ch_hi   = lane >> 4;

    int acc1[2][4][4];
    int accm[2][4][4];
#pragma unroll
    for (int mi = 0; mi < 2; mi++)
#pragma unroll
        for (int ni = 0; ni < 4; ni++)
#pragma unroll
            for (int j = 0; j < 4; j++) { acc1[mi][ni][j] = 0; accm[mi][ni][j] = 0; }

    auto compute = [&](int c) {
        const uint32_t st = sbase + (c % STAGES) * STAGE_BYTES;
#pragma unroll
        for (int kk = 0; kk < 2; kk++) {
            uint32_t a1[2][4], a0[2][4];
#pragma unroll
            for (int mi = 0; mi < 2; mi++) {
                const uint32_t o = tile_off(a_rbase + mi * 16, kk * 2 + ch_hi);
                ldsm4(a1[mi][0], a1[mi][1], a1[mi][2], a1[mi][3], st + OFF_A1 + o);
                ldsm4(a0[mi][0], a0[mi][1], a0[mi][2], a0[mi][3], st + OFF_A0 + o);
            }
            uint32_t b1[4][2], b0[4][2];
#pragma unroll
            for (int nj = 0; nj < 2; nj++) {
                const uint32_t o = tile_off(b_rbase + nj * 16, kk * 2 + ch_hi);
                uint32_t t0, t1, t2, t3;
                ldsm4(t0, t1, t2, t3, st + OFF_B1 + o);
                b1[2 * nj][0] = t0; b1[2 * nj + 1][0] = t1;
                b1[2 * nj][1] = t2; b1[2 * nj + 1][1] = t3;
                ldsm4(t0, t1, t2, t3, st + OFF_B0 + o);
                b0[2 * nj][0] = t0; b0[2 * nj + 1][0] = t1;
                b0[2 * nj][1] = t2; b0[2 * nj + 1][1] = t3;
            }
#pragma unroll
            for (int mi = 0; mi < 2; mi++)
#pragma unroll
                for (int ni = 0; ni < 4; ni++) {
                    mma_s8(acc1[mi][ni], a1[mi], b1[ni]);
                    mma_s8(accm[mi][ni], a1[mi], b0[ni]);
                    mma_s8(accm[mi][ni], a0[mi], b1[ni]);
                }
        }
    };

    load_stage(0); load_stage(1); load_stage(2);

    for (int c = 0; c < NC; c++) {
        CP_WAIT2();
        __syncthreads();
        if (c + STAGES - 1 < NC) load_stage(c + STAGES - 1);
        else                     CP_COMMIT();
        compute(c);
    }

    const float inv = 1.0f / (QSCALE * QSCALE);
    const int l4 = lane >> 2, l2 = (lane & 3) * 2;
#pragma unroll
    for (int mi = 0; mi < 2; mi++) {
        const long rg = bm + wm * 32 + mi * 16 + l4;
        const float sa0 = sA[rg] * inv;
        const float sa1 = sA[rg + 8] * inv;
#pragma unroll
        for (int ni = 0; ni < 4; ni++) {
            const long cg = bn + wn * 32 + ni * 8 + l2;
            const float sb0 = sB[cg], sb1 = sB[cg + 1];
            const float b0 = bias[cg], b1 = bias[cg + 1];
            const float f0 = 16384.0f * (float)acc1[mi][ni][0] + 128.0f * (float)accm[mi][ni][0];
            const float f1 = 16384.0f * (float)acc1[mi][ni][1] + 128.0f * (float)accm[mi][ni][1];
            const float f2 = 16384.0f * (float)acc1[mi][ni][2] + 128.0f * (float)accm[mi][ni][2];
            const float f3 = 16384.0f * (float)acc1[mi][ni][3] + 128.0f * (float)accm[mi][ni][3];
            float x0 = sa0 * sb0 * f0 + b0;
            float x1 = sa0 * sb1 * f1 + b1;
            float x2 = sa1 * sb0 * f2 + b0;
            float x3 = sa1 * sb1 * f3 + b1;
            if (ACT == 0) {
                x0 = fmaxf(x0, 0.f); x1 = fmaxf(x1, 0.f);
                x2 = fmaxf(x2, 0.f); x3 = fmaxf(x3, 0.f);
            } else {
                x0 = 1.f / (1.f + __expf(-x0));
                x1 = 1.f / (1.f + __expf(-x1));
                x2 = 1.f / (1.f + __expf(-x2));
                x3 = 1.f / (1.f + __expf(-x3));
            }
            *(float2*)&C[rg * (long)N + cg]       = make_float2(x0, x1);
            *(float2*)&C[(rg + 8) * (long)N + cg] = make_float2(x2, x3);
        }
    }
}

// ===========================================================================
// Column abs-max of W [K,N], split-K + atomicMax (nonneg: uint order = float).
// grid = (N/256, K/KCH), 256 threads, fully coalesced.
// Idempotent across graph replays (same input -> same max), so no init pass.
// ===========================================================================
#define KCH 256
__global__ void __launch_bounds__(256)
colmax_kernel(const float* __restrict__ W, float* __restrict__ s, int K, int N)
{
    const int col = blockIdx.x * 256 + threadIdx.x;
    const int k0 = blockIdx.y * KCH;
    const int k1 = min(k0 + KCH, K);
    float m = 0.0f;
    for (int k = k0; k < k1; k++)
        m = fmaxf(m, fabsf(W[(long)k * N + col]));
    atomicMax((unsigned*)&s[col], __float_as_uint(m));
}

// ===========================================================================
// W [K,N] -> Wt digits [N,K]: 64k x 32n tiles, packed 8B digit stores.
// ===========================================================================
__global__ void __launch_bounds__(256)
transpose_quant_kernel(const float* __restrict__ W, const float* __restrict__ s,
                       int8_t* __restrict__ Q1, int8_t* __restrict__ Q0,
                       int K, int N)
{
    __shared__ float t[64][33];
    const int tid = threadIdx.x;
    const long n0 = (long)blockIdx.x * 32, k0 = (long)blockIdx.y * 64;
    const int rn = tid & 31, rk = tid >> 5;    // read: 32 cols x 8 k-rows/iter
#pragma unroll
    for (int i = 0; i < 8; i++)
        t[rk + 8 * i][rn] = W[(k0 + rk + 8 * i) * N + n0 + rn];
    __syncthreads();

    const int col = tid >> 3;                  // 0..31
    const int kq  = (tid & 7) * 8;             // 0..56 step 8
    const long cg = n0 + col;
    const float sc = QSCALE / fmaxf(s[cg], 1e-20f);
    int8_t q1[8], q0[8];
#pragma unroll
    for (int i = 0; i < 8; i++)
        quant_dig(t[kq + i][col], sc, q1[i], q0[i]);
    const long o = cg * K + k0 + kq;
    *(uint2*)&Q1[o] = make_uint2(pack4(q1[0], q1[1], q1[2], q1[3]),
                                 pack4(q1[4], q1[5], q1[6], q1[7]));
    *(uint2*)&Q0[o] = make_uint2(pack4(q0[0], q0[1], q0[2], q0[3]),
                                 pack4(q0[4], q0[5], q0[6], q0[7]));
}

// ===========================================================================
// Per-row abs-max + quantize with smem row cache (single DRAM read of x).
// dynamic smem = K floats. Block per row.
// ===========================================================================
__global__ void __launch_bounds__(256)
quant_rows_kernel(const float* __restrict__ x, int8_t* __restrict__ Q1,
                  int8_t* __restrict__ Q0, float* __restrict__ sa, int K)
{
    extern __shared__ float row[];
    __shared__ float red[256];
    const long base = (long)blockIdx.x * K;
    const int tid = threadIdx.x;

    float m = 1e-20f;
    for (int i = tid * 4; i < K; i += 1024) {
        const float4 v = *(const float4*)&x[base + i];
        *(float4*)&row[i] = v;
        m = fmaxf(m, fmaxf(fmaxf(fabsf(v.x), fabsf(v.y)),
                           fmaxf(fabsf(v.z), fabsf(v.w))));
    }
    red[tid] = m;
    __syncthreads();
#pragma unroll
    for (int off = 128; off > 0; off >>= 1) {
        if (tid < off) red[tid] = fmaxf(red[tid], red[tid + off]);
        __syncthreads();
    }
    const float s = red[0];
    const float sc = QSCALE / s;
    for (int i = tid * 4; i < K; i += 1024) {
        int8_t q1[4], q0[4];
#pragma unroll
        for (int j = 0; j < 4; j++) quant_dig(row[i + j], sc, q1[j], q0[j]);
        *(uint32_t*)&Q1[base + i] = pack4(q1[0], q1[1], q1[2], q1[3]);
        *(uint32_t*)&Q0[base + i] = pack4(q0[0], q0[1], q0[2], q0[3]);
    }
    if (tid == 0) sa[blockIdx.x] = s;
}

// ===========================================================================
// Exact per-row top-64 keep (radix select, nonneg) + int8 digit output
// ===========================================================================
__global__ void __launch_bounds__(256)
topk64_quant_kernel(const float* __restrict__ h, int8_t* __restrict__ Q1,
                    int8_t* __restrict__ Q0, float* __restrict__ sa)
{
    __shared__ float vals[1024];
    __shared__ int hist[256];
    __shared__ float redm[256];
    __shared__ int s_k;
    __shared__ unsigned s_prefix;

    const float* row = h + (long)blockIdx.x * 1024;
    const int tid = threadIdx.x;

    float m = 1e-20f;
#pragma unroll
    for (int i = tid; i < 1024; i += 256) {
        const float v = row[i];
        vals[i] = v;
        m = fmaxf(m, v);
    }
    redm[tid] = m;
    if (tid == 0) { s_k = 64; s_prefix = 0u; }
    __syncthreads();
#pragma unroll
    for (int off = 128; off > 0; off >>= 1) {
        if (tid < off) redm[tid] = fmaxf(redm[tid], redm[tid + off]);
        __syncthreads();
    }
    const float smax = redm[0];

#pragma unroll
    for (int shift = 24; shift >= 0; shift -= 8) {
        hist[tid] = 0;
        __syncthreads();
        const unsigned hmask = (shift == 24) ? 0u : (0xFFFFFFFFu << (shift + 8));
        const unsigned pfx = s_prefix;
#pragma unroll
        for (int i = tid; i < 1024; i += 256) {
            const unsigned u = __float_as_uint(vals[i]);
            if ((u & hmask) == pfx)
                atomicAdd(&hist[(u >> shift) & 255], 1);
        }
        __syncthreads();
        if (tid == 0) {
            int k = s_k, cum = 0, d;
            for (d = 255; d > 0; d--) {
                const int c = hist[d];
                if (cum + c >= k) break;
                cum += c;
            }
            s_prefix = pfx | ((unsigned)d << shift);
            s_k = k - cum;
        }
        __syncthreads();
    }

    const float thr = __uint_as_float(s_prefix);
    const float sc = QSCALE / smax;
    const long base = (long)blockIdx.x * 1024;
#pragma unroll
    for (int i = tid; i < 1024; i += 256) {
        const float v = vals[i];
        const float kept = (v >= thr) ? v : 0.0f;
        int8_t q1, q0;
        quant_dig(kept, sc, q1, q0);
        Q1[base + i] = q1;
        Q0[base + i] = q0;
    }
    if (tid == 0) sa[blockIdx.x] = smax;
}

// ===========================================================================
extern "C" void kernel_launch(void* const* d_in, const int* in_sizes, int n_in,
                              void* d_out, int out_size)
{
    const float* X   = (const float*)d_in[0];   // [4096, 12288]
    const float* We1 = (const float*)d_in[1];   // [12288, 1024]
    const float* be1 = (const float*)d_in[2];
    const float* Wd1 = (const float*)d_in[3];   // [1024, 1024]
    const float* bd1 = (const float*)d_in[4];
    const float* Wd2 = (const float*)d_in[5];   // [1024, 12288]
    const float* bd2 = (const float*)d_in[6];
    float* out = (float*)d_out;                 // [4096, 12288]

    int8_t *X1, *X0, *W1q1, *W1q0, *W2q1, *W2q0, *W3q1, *W3q0, *h1, *h0, *d1, *d0;
    float *h, *d, *sX, *sh, *sd, *sW1, *sW2, *sW3;
    cudaGetSymbolAddress((void**)&X1, g_X1);     cudaGetSymbolAddress((void**)&X0, g_X0);
    cudaGetSymbolAddress((void**)&W1q1, g_W1q1); cudaGetSymbolAddress((void**)&W1q0, g_W1q0);
    cudaGetSymbolAddress((void**)&W2q1, g_W2q1); cudaGetSymbolAddress((void**)&W2q0, g_W2q0);
    cudaGetSymbolAddress((void**)&W3q1, g_W3q1); cudaGetSymbolAddress((void**)&W3q0, g_W3q0);
    cudaGetSymbolAddress((void**)&h1, g_h1);     cudaGetSymbolAddress((void**)&h0, g_h0);
    cudaGetSymbolAddress((void**)&d1, g_d1);     cudaGetSymbolAddress((void**)&d0, g_d0);
    cudaGetSymbolAddress((void**)&h, g_h);       cudaGetSymbolAddress((void**)&d, g_d);
    cudaGetSymbolAddress((void**)&sX, g_sX);     cudaGetSymbolAddress((void**)&sh, g_sh);
    cudaGetSymbolAddress((void**)&sd, g_sd);
    cudaGetSymbolAddress((void**)&sW1, g_sW1);   cudaGetSymbolAddress((void**)&sW2, g_sW2);
    cudaGetSymbolAddress((void**)&sW3, g_sW3);

    cudaFuncSetAttribute(gemm_i8<0>, cudaFuncAttributeMaxDynamicSharedMemorySize, SMEM_ALLOC);
    cudaFuncSetAttribute(gemm_i8<1>, cudaFuncAttributeMaxDynamicSharedMemorySize, SMEM_ALLOC);
    cudaFuncSetAttribute(quant_rows_kernel, cudaFuncAttributeMaxDynamicSharedMemorySize, 12288 * 4);

    const int M = 4096, HID = 1024, D = 12288;

    // ---- operand prep ----
    colmax_kernel<<<dim3(HID / 256, D / KCH), 256>>>(We1, sW1, D, HID);
    colmax_kernel<<<dim3(HID / 256, HID / KCH), 256>>>(Wd1, sW2, HID, HID);
    colmax_kernel<<<dim3(D / 256, HID / KCH), 256>>>(Wd2, sW3, HID, D);
    transpose_quant_kernel<<<dim3(HID / 32, D / 64), 256>>>(We1, sW1, W1q1, W1q0, D, HID);
    transpose_quant_kernel<<<dim3(HID / 32, HID / 64), 256>>>(Wd1, sW2, W2q1, W2q0, HID, HID);
    transpose_quant_kernel<<<dim3(D / 32, HID / 64), 256>>>(Wd2, sW3, W3q1, W3q0, HID, D);
    quant_rows_kernel<<<M, 256, D * 4>>>(X, X1, X0, sX, D);

    // ---- layer 1: h = relu(X @ We1 + be1) ----
    gemm_i8<0><<<dim3(HID / BN, M / BM), NTHREADS, SMEM_ALLOC>>>(
        X1, X0, W1q1, W1q0, sX, sW1, be1, h, M, HID, D);
    // ---- top-64 keep + quantize ----
    topk64_quant_kernel<<<M, 256>>>(h, h1, h0, sh);
    // ---- layer 2: d = relu(h @ Wd1 + bd1) ----
    gemm_i8<0><<<dim3(HID / BN, M / BM), NTHREADS, SMEM_ALLOC>>>(
        h1, h0, W2q1, W2q0, sh, sW2, bd1, d, M, HID, HID);
    quant_rows_kernel<<<M, 256, HID * 4>>>(d, d1, d0, sd, HID);
    // ---- layer 3: out = sigmoid(d @ Wd2 + bd2) ----
    gemm_i8<1><<<dim3(D / BN, M / BM), NTHREADS, SMEM_ALLOC>>>(
        d1, d0, W3q1, W3q0, sd, sW3, bd2, out, M, D, HID);
}